// round 7
// baseline (speedup 1.0000x reference)
#include <cuda_runtime.h>
#include <cuda_fp16.h>
#include <cstdint>

// ============================================================================
// out[16384,1024] = (W0[idx] @ W1) * (idx != 0) * 32.0
//
// Round 7 (compute_100 virtual arch: sm_80 mma path):
//   prep: blocks < TOKENS gather W0 rows -> fp16 A16 (mask & *32 folded),
//         one uint4 store/thread; remaining blocks transpose W1 -> Bt.
//   gemm: dense fp16 m16n8k16. CTA tile 128x64 (BN 128->64) => grid 2048
//         => 6.92 waves at 2 CTAs/SM => 98.9% wave efficiency (was 86.5%
//         at 3.46->4 waves). 8 warps, layout 4M x 2N, warp tile 32x32.
//         STAGES=3 (72KB smem), ring unrolled by period 3.
// ============================================================================

namespace {

constexpr int TOKENS = 16384;
constexpr int KDIM   = 2048;
constexpr int HDIM   = 1024;

constexpr int BM = 128;
constexpr int BN = 64;
constexpr int BK = 64;              // 64 halfs = 128 B rows
constexpr int KITERS = KDIM / BK;   // 32

constexpr int THREADS = 256;        // 8 warps: 4 (M) x 2 (N), warp tile 32x32

constexpr uint32_t A_STAGE_BYTES = BM * 128;                       // 16 KB
constexpr uint32_t B_STAGE_BYTES = BN * 128;                       // 8 KB
constexpr uint32_t STAGE_BYTES   = A_STAGE_BYTES + B_STAGE_BYTES;  // 24 KB
constexpr uint32_t SMEM_TOTAL    = 3 * STAGE_BYTES;                // 72 KB

constexpr int PREP_B_BLOCKS = (HDIM / 32) * (KDIM / 32);           // 2048

__device__ __half g_A16[(size_t)TOKENS * KDIM];  // gathered, masked, *32
__device__ __half g_Bt[(size_t)HDIM * KDIM];     // W1^T, K-major

// ---------------------------------------------------------------------------
// helpers
// ---------------------------------------------------------------------------
__device__ __forceinline__ uint32_t smem_u32(const void* p) {
    uint32_t a;
    asm("{ .reg .u64 t; cvta.to.shared.u64 t, %1; cvt.u32.u64 %0, t; }"
        : "=r"(a) : "l"(p));
    return a;
}

#define CP_ASYNC16(dst, src) \
    asm volatile("cp.async.cg.shared.global [%0], [%1], 16;" \
                 :: "r"(dst), "l"(src) : "memory")
#define CP_COMMIT() asm volatile("cp.async.commit_group;" ::: "memory")
#define CP_WAIT(n)  asm volatile("cp.async.wait_group %0;" :: "n"(n) : "memory")

#define LDMX4(r, addr)                                                        \
    asm volatile("ldmatrix.sync.aligned.m8n8.x4.shared.b16 {%0,%1,%2,%3}, [%4];" \
        : "=r"((r)[0]), "=r"((r)[1]), "=r"((r)[2]), "=r"((r)[3])              \
        : "r"(addr))

__device__ __forceinline__ void mma_f16(float* d, const uint32_t* a,
                                        const uint32_t* b) {
    asm volatile(
        "mma.sync.aligned.m16n8k16.row.col.f32.f16.f16.f32 "
        "{%0,%1,%2,%3}, {%4,%5,%6,%7}, {%8,%9}, {%0,%1,%2,%3};"
        : "+f"(d[0]), "+f"(d[1]), "+f"(d[2]), "+f"(d[3])
        : "r"(a[0]), "r"(a[1]), "r"(a[2]), "r"(a[3]), "r"(b[0]), "r"(b[1]));
}

// ---------------------------------------------------------------------------
// prep: gather/convert A (blocks 0..TOKENS-1) + transpose W1 (the rest)
// ---------------------------------------------------------------------------
__global__ __launch_bounds__(256)
void prep(const int* __restrict__ inputs, const float* __restrict__ W0,
          const float* __restrict__ W1) {
    __shared__ float tile[32][33];
    const int bid = blockIdx.x;
    const int tid = threadIdx.x;

    if (bid < TOKENS) {
        const int tok = inputs[bid];
        const float sc = (tok != 0) ? 32.0f : 0.0f;
        const float4* src =
            reinterpret_cast<const float4*>(W0 + (size_t)tok * KDIM);
        uint4* dst = reinterpret_cast<uint4*>(g_A16 + (size_t)bid * KDIM);
        float4 v0 = src[2 * tid];
        float4 v1 = src[2 * tid + 1];
        __half2 h0 = __floats2half2_rn(v0.x * sc, v0.y * sc);
        __half2 h1 = __floats2half2_rn(v0.z * sc, v0.w * sc);
        __half2 h2 = __floats2half2_rn(v1.x * sc, v1.y * sc);
        __half2 h3 = __floats2half2_rn(v1.z * sc, v1.w * sc);
        uint4 u;
        u.x = *reinterpret_cast<uint32_t*>(&h0);
        u.y = *reinterpret_cast<uint32_t*>(&h1);
        u.z = *reinterpret_cast<uint32_t*>(&h2);
        u.w = *reinterpret_cast<uint32_t*>(&h3);
        dst[tid] = u;
    } else {
        const int bid2 = bid - TOKENS;
        const int n0 = (bid2 & 31) * 32;
        const int k0 = (bid2 >> 5) * 32;
        const int tx = tid & 31;
        const int tyb = tid >> 5;
#pragma unroll
        for (int dy = 0; dy < 32; dy += 8) {
            int ty = tyb + dy;
            tile[ty][tx] = W1[(size_t)(k0 + ty) * HDIM + n0 + tx];
        }
        __syncthreads();
#pragma unroll
        for (int dy = 0; dy < 32; dy += 8) {
            int ty = tyb + dy;
            g_Bt[(size_t)(n0 + ty) * KDIM + k0 + tx] =
                __float2half_rn(tile[tx][ty]);
        }
    }
}

// ---------------------------------------------------------------------------
// main dense fp16 GEMM: out[16384,1024] = A16 @ Bt^T   (fp32 accumulate)
// ---------------------------------------------------------------------------
__global__ __launch_bounds__(THREADS, 2)
void gemm_f16(float* __restrict__ out) {
    extern __shared__ char smem[];
    const uint32_t smem_base = smem_u32(smem);

    const int tid  = threadIdx.x;
    const int lane = tid & 31;
    const int wid  = tid >> 5;

    const int mtile  = blockIdx.x >> 4;   // 0..127
    const int ntile  = blockIdx.x & 15;   // 0..15
    const int m_base = mtile * BM;
    const int n_base = ntile * BN;

    const __half* aG = g_A16 + (size_t)m_base * KDIM;
    const __half* bG = g_Bt + (size_t)n_base * KDIM;

    // stage issue: A 1024 chunks (4/thread), B 512 chunks (2/thread)
    auto issue = [&](int kt, uint32_t stage) {
        const int koff = kt * BK;
#pragma unroll
        for (int i = 0; i < 4; i++) {
            const int c = tid + 256 * i;
            const int row = c >> 3, ch = c & 7;
            const uint32_t dst = smem_base + stage + (uint32_t)row * 128u +
                                 (uint32_t)((ch ^ (row & 7)) * 16);
            CP_ASYNC16(dst, aG + (size_t)row * KDIM + koff + ch * 8);
        }
#pragma unroll
        for (int i = 0; i < 2; i++) {
            const int c = tid + 256 * i;
            const int row = c >> 3, ch = c & 7;
            const uint32_t dst = smem_base + stage + A_STAGE_BYTES +
                                 (uint32_t)row * 128u +
                                 (uint32_t)((ch ^ (row & 7)) * 16);
            CP_ASYNC16(dst, bG + (size_t)row * KDIM + koff + ch * 8);
        }
    };

    // ---- fragment addressing ----
    const int wm = (wid >> 1) * 32;   // warp M offset (0/32/64/96)
    const int wn = (wid & 1) * 32;    // warp N offset (0/32)
    const int arF = (lane & 7) + (((lane >> 3) & 1) << 3);
    const uint32_t acp = (uint32_t)(lane >> 4);
    const uint32_t asw = (uint32_t)(lane & 7);
    uint32_t rowA[2];
#pragma unroll
    for (int mt = 0; mt < 2; mt++)
        rowA[mt] = smem_base + (uint32_t)(wm + 16 * mt + arF) * 128u;
    const int brF = (lane & 7) + (((lane >> 4) & 1) << 3);
    const uint32_t bcp = (uint32_t)((lane >> 3) & 1);
    const uint32_t bsw = (uint32_t)(lane & 7);
    uint32_t rowB[2];
#pragma unroll
    for (int g = 0; g < 2; g++)
        rowB[g] = smem_base + A_STAGE_BYTES +
                  (uint32_t)(wn + 16 * g + brF) * 128u;

    float acc[2][4][4];
#pragma unroll
    for (int mt = 0; mt < 2; mt++)
#pragma unroll
        for (int nt = 0; nt < 4; nt++)
#pragma unroll
            for (int i = 0; i < 4; i++) acc[mt][nt][i] = 0.0f;

    // ---- prologue: kt=0 -> slot0, kt=1 -> slot1 ----
    issue(0, 0);
    CP_COMMIT();
    issue(1, STAGE_BYTES);
    CP_COMMIT();

    // one pipeline step: consume kt from `stage`, produce kt+2 into `prod`
    auto body = [&](int kt, uint32_t stage, uint32_t prod) {
        CP_WAIT(1);
        __syncthreads();

        if (kt + 2 < KITERS) issue(kt + 2, prod);
        CP_COMMIT();

#pragma unroll
        for (int ks = 0; ks < 4; ks++) {   // 4 x k16 per ktile
            const uint32_t ak = (((uint32_t)(2 * ks) + acp) ^ asw) * 16u + stage;
            const uint32_t bk = (((uint32_t)(2 * ks) + bcp) ^ bsw) * 16u + stage;

            uint32_t b[2][4];
#pragma unroll
            for (int g = 0; g < 2; g++) LDMX4(b[g], rowB[g] + bk);
#pragma unroll
            for (int mt = 0; mt < 2; mt++) {
                uint32_t a[4];
                LDMX4(a, rowA[mt] + ak);
#pragma unroll
                for (int nt = 0; nt < 4; nt++)
                    mma_f16(acc[mt][nt], a, &b[nt >> 1][(nt & 1) * 2]);
            }
        }
    };

    // ---- main loop: ring period 3, compile-time stage offsets ----
    constexpr uint32_t S0 = 0, S1 = STAGE_BYTES, S2 = 2 * STAGE_BYTES;
    for (int base = 0; base < 30; base += 3) {
        body(base + 0, S0, S2);
        body(base + 1, S1, S0);
        body(base + 2, S2, S1);
    }
    body(30, S0, S2);   // kt=30, no issue
    body(31, S1, S0);   // kt=31, no issue

    // ---- epilogue: mask & scale already folded into A ----
#pragma unroll
    for (int mt = 0; mt < 2; mt++) {
        const int r0 = m_base + wm + 16 * mt + (lane >> 2);
        const int r1 = r0 + 8;
        float* o0 = out + (size_t)r0 * HDIM + n_base + wn + 2 * (lane & 3);
        float* o1 = out + (size_t)r1 * HDIM + n_base + wn + 2 * (lane & 3);
#pragma unroll
        for (int nt = 0; nt < 4; nt++) {
            *reinterpret_cast<float2*>(o0 + nt * 8) =
                make_float2(acc[mt][nt][0], acc[mt][nt][1]);
            *reinterpret_cast<float2*>(o1 + nt * 8) =
                make_float2(acc[mt][nt][2], acc[mt][nt][3]);
        }
    }
}

}  // anonymous namespace

// ---------------------------------------------------------------------------
extern "C" void kernel_launch(void* const* d_in, const int* in_sizes, int n_in,
                              void* d_out, int out_size) {
    const int*   inputs = (const int*)d_in[0];
    const float* W0     = (const float*)d_in[1];
    const float* W1     = (const float*)d_in[2];
    float*       out    = (float*)d_out;
    (void)in_sizes; (void)n_in; (void)out_size;

    cudaFuncSetAttribute(gemm_f16,
                         cudaFuncAttributeMaxDynamicSharedMemorySize,
                         SMEM_TOTAL);

    prep<<<TOKENS + PREP_B_BLOCKS, 256>>>(inputs, W0, W1);

    const int grid = (TOKENS / BM) * (HDIM / BN);   // 128 * 16 = 2048
    gemm_f16<<<grid, THREADS, SMEM_TOTAL>>>(out);
}

// round 8
// speedup vs baseline: 1.0786x; 1.0786x over previous
#include <cuda_runtime.h>
#include <cuda_fp16.h>
#include <cstdint>

// ============================================================================
// out[16384,1024] = (W0[idx] @ W1) * (idx != 0) * 32.0
//
// Round 8 (compute_100 virtual arch: sm_80 mma path):
//   prep: gather W0 rows -> fp16 A16 (mask & *32 folded) + transpose W1 -> Bt.
//   gemm: dense fp16 m16n8k16. CTA tile 64x128, 4 warps (warp tile 32x64,
//         same 6:16 LDSM:MMA ratio as the best 196us config), STAGES=3
//         (72KB smem) -> 3 CTAs/SM -> 444 slots, grid 2048 -> 4.61->5 waves
//         (92.2% vs 86.5%), and T_tile halved so drain costs half.
// ============================================================================

namespace {

constexpr int TOKENS = 16384;
constexpr int KDIM   = 2048;
constexpr int HDIM   = 1024;

constexpr int BM = 64;
constexpr int BN = 128;
constexpr int BK = 64;              // 64 halfs = 128 B rows
constexpr int KITERS = KDIM / BK;   // 32

constexpr int THREADS = 128;        // 4 warps: 2 (M) x 2 (N), warp tile 32x64

constexpr uint32_t A_STAGE_BYTES = BM * 128;                       // 8 KB
constexpr uint32_t B_STAGE_BYTES = BN * 128;                       // 16 KB
constexpr uint32_t STAGE_BYTES   = A_STAGE_BYTES + B_STAGE_BYTES;  // 24 KB
constexpr uint32_t SMEM_TOTAL    = 3 * STAGE_BYTES;                // 72 KB

constexpr int PREP_B_BLOCKS = (HDIM / 32) * (KDIM / 32);           // 2048

__device__ __half g_A16[(size_t)TOKENS * KDIM];  // gathered, masked, *32
__device__ __half g_Bt[(size_t)HDIM * KDIM];     // W1^T, K-major

// ---------------------------------------------------------------------------
// helpers
// ---------------------------------------------------------------------------
__device__ __forceinline__ uint32_t smem_u32(const void* p) {
    uint32_t a;
    asm("{ .reg .u64 t; cvta.to.shared.u64 t, %1; cvt.u32.u64 %0, t; }"
        : "=r"(a) : "l"(p));
    return a;
}

#define CP_ASYNC16(dst, src) \
    asm volatile("cp.async.cg.shared.global [%0], [%1], 16;" \
                 :: "r"(dst), "l"(src) : "memory")
#define CP_COMMIT() asm volatile("cp.async.commit_group;" ::: "memory")
#define CP_WAIT(n)  asm volatile("cp.async.wait_group %0;" :: "n"(n) : "memory")

#define LDMX4(r, addr)                                                        \
    asm volatile("ldmatrix.sync.aligned.m8n8.x4.shared.b16 {%0,%1,%2,%3}, [%4];" \
        : "=r"((r)[0]), "=r"((r)[1]), "=r"((r)[2]), "=r"((r)[3])              \
        : "r"(addr))

__device__ __forceinline__ void mma_f16(float* d, const uint32_t* a,
                                        const uint32_t* b) {
    asm volatile(
        "mma.sync.aligned.m16n8k16.row.col.f32.f16.f16.f32 "
        "{%0,%1,%2,%3}, {%4,%5,%6,%7}, {%8,%9}, {%0,%1,%2,%3};"
        : "+f"(d[0]), "+f"(d[1]), "+f"(d[2]), "+f"(d[3])
        : "r"(a[0]), "r"(a[1]), "r"(a[2]), "r"(a[3]), "r"(b[0]), "r"(b[1]));
}

// ---------------------------------------------------------------------------
// prep: gather/convert A (blocks 0..TOKENS-1) + transpose W1 (the rest)
// ---------------------------------------------------------------------------
__global__ __launch_bounds__(256)
void prep(const int* __restrict__ inputs, const float* __restrict__ W0,
          const float* __restrict__ W1) {
    __shared__ float tile[32][33];
    const int bid = blockIdx.x;
    const int tid = threadIdx.x;

    if (bid < TOKENS) {
        const int tok = inputs[bid];
        const float sc = (tok != 0) ? 32.0f : 0.0f;
        const float4* src =
            reinterpret_cast<const float4*>(W0 + (size_t)tok * KDIM);
        uint4* dst = reinterpret_cast<uint4*>(g_A16 + (size_t)bid * KDIM);
        float4 v0 = src[2 * tid];
        float4 v1 = src[2 * tid + 1];
        __half2 h0 = __floats2half2_rn(v0.x * sc, v0.y * sc);
        __half2 h1 = __floats2half2_rn(v0.z * sc, v0.w * sc);
        __half2 h2 = __floats2half2_rn(v1.x * sc, v1.y * sc);
        __half2 h3 = __floats2half2_rn(v1.z * sc, v1.w * sc);
        uint4 u;
        u.x = *reinterpret_cast<uint32_t*>(&h0);
        u.y = *reinterpret_cast<uint32_t*>(&h1);
        u.z = *reinterpret_cast<uint32_t*>(&h2);
        u.w = *reinterpret_cast<uint32_t*>(&h3);
        dst[tid] = u;
    } else {
        const int bid2 = bid - TOKENS;
        const int n0 = (bid2 & 31) * 32;
        const int k0 = (bid2 >> 5) * 32;
        const int tx = tid & 31;
        const int tyb = tid >> 5;
#pragma unroll
        for (int dy = 0; dy < 32; dy += 8) {
            int ty = tyb + dy;
            tile[ty][tx] = W1[(size_t)(k0 + ty) * HDIM + n0 + tx];
        }
        __syncthreads();
#pragma unroll
        for (int dy = 0; dy < 32; dy += 8) {
            int ty = tyb + dy;
            g_Bt[(size_t)(n0 + ty) * KDIM + k0 + tx] =
                __float2half_rn(tile[tx][ty]);
        }
    }
}

// ---------------------------------------------------------------------------
// main dense fp16 GEMM: out[16384,1024] = A16 @ Bt^T   (fp32 accumulate)
// ---------------------------------------------------------------------------
__global__ __launch_bounds__(THREADS, 3)
void gemm_f16(float* __restrict__ out) {
    extern __shared__ char smem[];
    const uint32_t smem_base = smem_u32(smem);

    const int tid  = threadIdx.x;
    const int lane = tid & 31;
    const int wid  = tid >> 5;

    const int mtile  = blockIdx.x >> 3;   // 0..255
    const int ntile  = blockIdx.x & 7;    // 0..7
    const int m_base = mtile * BM;
    const int n_base = ntile * BN;

    const __half* aG = g_A16 + (size_t)m_base * KDIM;
    const __half* bG = g_Bt + (size_t)n_base * KDIM;

    // stage issue: A 512 chunks (4/thread), B 1024 chunks (8/thread)
    auto issue = [&](int kt, uint32_t stage) {
        const int koff = kt * BK;
#pragma unroll
        for (int i = 0; i < 4; i++) {
            const int c = tid + 128 * i;
            const int row = c >> 3, ch = c & 7;
            const uint32_t dst = smem_base + stage + (uint32_t)row * 128u +
                                 (uint32_t)((ch ^ (row & 7)) * 16);
            CP_ASYNC16(dst, aG + (size_t)row * KDIM + koff + ch * 8);
        }
#pragma unroll
        for (int i = 0; i < 8; i++) {
            const int c = tid + 128 * i;
            const int row = c >> 3, ch = c & 7;
            const uint32_t dst = smem_base + stage + A_STAGE_BYTES +
                                 (uint32_t)row * 128u +
                                 (uint32_t)((ch ^ (row & 7)) * 16);
            CP_ASYNC16(dst, bG + (size_t)row * KDIM + koff + ch * 8);
        }
    };

    // ---- fragment addressing ----
    const int wm = (wid & 1) * 32;    // warp M offset (0/32)
    const int wn = (wid >> 1) * 64;   // warp N offset (0/64)
    const int arF = (lane & 7) + (((lane >> 3) & 1) << 3);
    const uint32_t acp = (uint32_t)(lane >> 4);
    const uint32_t asw = (uint32_t)(lane & 7);
    uint32_t rowA[2];
#pragma unroll
    for (int mt = 0; mt < 2; mt++)
        rowA[mt] = smem_base + (uint32_t)(wm + 16 * mt + arF) * 128u;
    const int brF = (lane & 7) + (((lane >> 4) & 1) << 3);
    const uint32_t bcp = (uint32_t)((lane >> 3) & 1);
    const uint32_t bsw = (uint32_t)(lane & 7);
    uint32_t rowB[4];
#pragma unroll
    for (int g = 0; g < 4; g++)
        rowB[g] = smem_base + A_STAGE_BYTES +
                  (uint32_t)(wn + 16 * g + brF) * 128u;

    float acc[2][8][4];
#pragma unroll
    for (int mt = 0; mt < 2; mt++)
#pragma unroll
        for (int nt = 0; nt < 8; nt++)
#pragma unroll
            for (int i = 0; i < 4; i++) acc[mt][nt][i] = 0.0f;

    // ---- prologue: kt=0 -> slot0, kt=1 -> slot1 ----
    issue(0, 0);
    CP_COMMIT();
    issue(1, STAGE_BYTES);
    CP_COMMIT();

    // one pipeline step: consume kt from `stage`, produce kt+2 into `prod`
    auto body = [&](int kt, uint32_t stage, uint32_t prod) {
        CP_WAIT(1);
        __syncthreads();

        if (kt + 2 < KITERS) issue(kt + 2, prod);
        CP_COMMIT();

#pragma unroll
        for (int ks = 0; ks < 4; ks++) {   // 4 x k16 per ktile
            const uint32_t ak = (((uint32_t)(2 * ks) + acp) ^ asw) * 16u + stage;
            const uint32_t bk = (((uint32_t)(2 * ks) + bcp) ^ bsw) * 16u + stage;

            uint32_t b[4][4];
#pragma unroll
            for (int g = 0; g < 4; g++) LDMX4(b[g], rowB[g] + bk);
#pragma unroll
            for (int mt = 0; mt < 2; mt++) {
                uint32_t a[4];
                LDMX4(a, rowA[mt] + ak);
#pragma unroll
                for (int nt = 0; nt < 8; nt++)
                    mma_f16(acc[mt][nt], a, &b[nt >> 1][(nt & 1) * 2]);
            }
        }
    };

    // ---- main loop: ring period 3, compile-time stage offsets ----
    constexpr uint32_t S0 = 0, S1 = STAGE_BYTES, S2 = 2 * STAGE_BYTES;
    for (int base = 0; base < 30; base += 3) {
        body(base + 0, S0, S2);
        body(base + 1, S1, S0);
        body(base + 2, S2, S1);
    }
    body(30, S0, S2);   // kt=30, no issue
    body(31, S1, S0);   // kt=31, no issue

    // ---- epilogue: mask & scale already folded into A ----
#pragma unroll
    for (int mt = 0; mt < 2; mt++) {
        const int r0 = m_base + wm + 16 * mt + (lane >> 2);
        const int r1 = r0 + 8;
        float* o0 = out + (size_t)r0 * HDIM + n_base + wn + 2 * (lane & 3);
        float* o1 = out + (size_t)r1 * HDIM + n_base + wn + 2 * (lane & 3);
#pragma unroll
        for (int nt = 0; nt < 8; nt++) {
            *reinterpret_cast<float2*>(o0 + nt * 8) =
                make_float2(acc[mt][nt][0], acc[mt][nt][1]);
            *reinterpret_cast<float2*>(o1 + nt * 8) =
                make_float2(acc[mt][nt][2], acc[mt][nt][3]);
        }
    }
}

}  // anonymous namespace

// ---------------------------------------------------------------------------
extern "C" void kernel_launch(void* const* d_in, const int* in_sizes, int n_in,
                              void* d_out, int out_size) {
    const int*   inputs = (const int*)d_in[0];
    const float* W0     = (const float*)d_in[1];
    const float* W1     = (const float*)d_in[2];
    float*       out    = (float*)d_out;
    (void)in_sizes; (void)n_in; (void)out_size;

    cudaFuncSetAttribute(gemm_f16,
                         cudaFuncAttributeMaxDynamicSharedMemorySize,
                         SMEM_TOTAL);

    prep<<<TOKENS + PREP_B_BLOCKS, 256>>>(inputs, W0, W1);

    const int grid = (TOKENS / BM) * (HDIM / BN);   // 256 * 8 = 2048
    gemm_f16<<<grid, THREADS, SMEM_TOTAL>>>(out);
}